// round 14
// baseline (speedup 1.0000x reference)
#include <cuda_runtime.h>
#include <cstdint>
#include <cstddef>

#define B   32
#define T   2048
#define E   512
#define H   512
#define G4  2048
#define NCTA 128
#define THREADS 576          // 512 recurrence + 64 GEMM
#define HS_STRIDE  516
#define HS_STRIDE4 129

#define SM_RED_BASE   (48 * HS_STRIDE)
#define SM_GEMM_BASE  (SM_RED_BASE + 2 * 512 * 4)     // floats
#define GEMM_AS_STRIDE 68
#define GEMM_BS_STRIDE 72
#define SM_GEMM_FLOATS (16 * GEMM_AS_STRIDE + 16 * GEMM_BS_STRIDE)

// ---- device scratch ----
__device__ float g_xg[(size_t)B * T * G4];
__device__ float g_hbuf[2][2][16 * H];
__device__ unsigned g_bar[2];        // per-team recurrence arrival counters
__device__ unsigned g_chunk[16];     // per-128-timestep xg readiness counters

__device__ __forceinline__ void barn(int id, int cnt) {
    asm volatile("bar.sync %0, %1;" :: "r"(id), "r"(cnt) : "memory");
}
__device__ __forceinline__ unsigned ld_acq(const unsigned* p) {
    unsigned v;
    asm volatile("ld.acquire.gpu.global.u32 %0, [%1];" : "=r"(v) : "l"(p));
    return v;
}
__device__ __forceinline__ void red_release_add(unsigned* p, unsigned v) {
    asm volatile("red.release.gpu.global.add.u32 [%0], %1;" :: "l"(p), "r"(v)
                 : "memory");
}
__device__ __forceinline__ float sigm(float x) {
    return 1.f / (1.f + __expf(-x));
}
__device__ __forceinline__ float tanh_fast(float x) {
    return 2.f / (1.f + __expf(-2.f * x)) - 1.f;
}

__global__ void reset_ctr_kernel() {
    if (threadIdx.x < 2)  g_bar[threadIdx.x] = 0;
    if (threadIdx.x < 16) g_chunk[threadIdx.x] = 0;
}

// =====================================================================
// Fused persistent kernel. 128 CTAs x 576 threads.
//  warps 0-15 : recurrence (two SMT teams of 8 warps / 16 batches)
//  warps 16-17: xg GEMM producer — 64x64 tiles, 8m x 8n per thread
//               (half the LDS-per-FMA and half the threads of R13's
//               GEMM => ~0.5x crossbar load), software-pipelined LDG.
// =====================================================================
__global__ __launch_bounds__(THREADS, 1) void lstm_fused_kernel(
    const float* __restrict__ X,  const float* __restrict__ Wx,
    const float* __restrict__ Wh, const float* __restrict__ bx,
    const float* __restrict__ bh, float* __restrict__ out)
{
    extern __shared__ float sm[];
    float* whs = sm;                       // 16 x 516

    const int tid  = threadIdx.x;
    const int cta  = blockIdx.x;

    // ---- common init ----
    for (int idx = tid; idx < 16 * 512; idx += THREADS) {
        int c = idx >> 9;
        int k = idx & 511;
        int col = ((c >> 2) << 9) + cta * 4 + (c & 3);
        whs[c * HS_STRIDE + k] = Wh[(size_t)k * G4 + col];
    }
    for (int idx = tid; idx < 32 * HS_STRIDE; idx += THREADS)
        sm[16 * HS_STRIDE + idx] = 0.f;
    __syncthreads();   // the only full-block sync

    if (tid < 512) {
        // =========================== RECURRENCE ======================
        const int team  = tid >> 8;
        const int tt    = tid & 255;
        const int lane  = tid & 31;
        const int wteam = tt >> 5;

        float*  hslot = sm + (16 + team * 16) * HS_STRIDE;
        float4* redt  = (float4*)(sm + SM_RED_BASE) + team * 512;

        const int lb = lane & 7;
        const int lc = lane >> 3;
        const float4* whs4 = (const float4*)whs;
        const float4* hs4  = (const float4*)hslot;
        float4*       hs4w = (float4*)hslot;

        const int bl    = tt >> 2;
        const int hl    = tt & 3;
        const int hid   = cta * 4 + hl;
        const int bglob = team * 16 + bl;
        float c_state = 0.f;

        const int barT = 1 + team;   // 256 threads
        const int barR = 3 + team;   // 64 threads

        for (int t = 0; t < T; t++) {
            if ((t & 127) == 0) {
                if (tt == 0) {
                    const unsigned* cc = &g_chunk[t >> 7];
                    int spins = 0;
                    while (ld_acq(cc) < 1024u) {
                        if (++spins > 16) __nanosleep(128);
                    }
                }
                barn(barT, 256);
            }

            float xp0 = 0.f, xp1 = 0.f, xp2 = 0.f, xp3 = 0.f;
            if (tt < 64) {
                const float* xr = g_xg + ((size_t)bglob * T + t) * G4 + hid;
                xp0 = __ldcs(xr);
                xp1 = __ldcs(xr + 512);
                xp2 = __ldcs(xr + 1024);
                xp3 = __ldcs(xr + 1536);
            }

            if (t > 0) {
                if (tt == 0) {
                    unsigned target = 128u * (unsigned)t;
                    int spins = 0;
                    while (ld_acq(&g_bar[team]) < target) {
                        if (++spins > 64) __nanosleep(64);
                    }
                }
                barn(barT, 256);
                const float4* src = (const float4*)g_hbuf[team][(t - 1) & 1];
                #pragma unroll
                for (int q = 0; q < 8; q++) {
                    int v  = tt + 256 * q;
                    int b  = v >> 7;
                    int kk = v & 127;
                    hs4w[b * HS_STRIDE4 + kk] = __ldcg(src + v);
                }
                barn(barT, 256);
            }

            float acc[2][4];
            #pragma unroll
            for (int j = 0; j < 2; j++)
                #pragma unroll
                for (int i = 0; i < 4; i++) acc[j][i] = 0.f;

            const int kb = wteam * 16;
            #pragma unroll 4
            for (int q = 0; q < 16; q++) {
                const int kv = kb + q;
                float4 wv[4];
                #pragma unroll
                for (int i = 0; i < 4; i++)
                    wv[i] = whs4[(lc + 4 * i) * HS_STRIDE4 + kv];
                #pragma unroll
                for (int j = 0; j < 2; j++) {
                    float4 hh = hs4[(lb + 8 * j) * HS_STRIDE4 + kv];
                    #pragma unroll
                    for (int i = 0; i < 4; i++) {
                        acc[j][i] = fmaf(hh.x, wv[i].x, acc[j][i]);
                        acc[j][i] = fmaf(hh.y, wv[i].y, acc[j][i]);
                        acc[j][i] = fmaf(hh.z, wv[i].z, acc[j][i]);
                        acc[j][i] = fmaf(hh.w, wv[i].w, acc[j][i]);
                    }
                }
            }

            #pragma unroll
            for (int j = 0; j < 2; j++)
                redt[wteam * 64 + (lb + 8 * j) * 4 + lc] =
                    make_float4(acc[j][0], acc[j][1], acc[j][2], acc[j][3]);
            barn(barT, 256);

            if (tt < 64) {
                float4 s = make_float4(0.f, 0.f, 0.f, 0.f);
                #pragma unroll
                for (int w = 0; w < 8; w++) {
                    float4 v = redt[w * 64 + tt];
                    s.x += v.x; s.y += v.y; s.z += v.z; s.w += v.w;
                }
                float f  = sigm(s.x + xp0);
                float ig = sigm(s.y + xp1);
                float cc = tanh_fast(s.z + xp2);
                float og = sigm(s.w + xp3);
                c_state = f * c_state + ig * cc;
                float h_new = og * tanh_fast(c_state);
                g_hbuf[team][t & 1][bl * H + hid] = h_new;
                if (t == T - 1) {
                    out[bglob * H + hid]         = h_new;
                    out[B * H + bglob * H + hid] = c_state;
                }
                barn(barR, 64);
                if (tt == 0) red_release_add(&g_bar[team], 1u);
            }
        }
    } else {
        // ============================ GEMM ===========================
        // warps 16-17 (64 threads). 64x64 tiles, 8m x 8n per thread.
        // Chunk tq needs tiles j = cta + (i<<7), i=0..15 (16 per CTA);
        // counter target per chunk = 128 CTAs * 8 releases?  NO — one
        // release per tile pair: we release once per 2 tiles to halve
        // counter ops: target 1024 = 128 CTAs * 8 (release every 2nd).
        const int gt = tid - 512;                    // 0..63
        float* As = sm + SM_GEMM_BASE;               // [16][68]  (k,m)
        float* Bs = As + 16 * GEMM_AS_STRIDE;        // [16][72]  (k,n)

        const int tm = (gt >> 3) * 8;
        const int tn = (gt & 7) * 8;
        const int brg = gt >> 4;                     // 0..3 B col group
        const int brr = gt & 15;                     // B k-row

        for (int tile = 0; tile < 256; tile++) {
            const int tq = tile >> 4;
            const int j  = cta + ((tile & 15) << 7);
            const int mtl = j >> 5;
            const int nt  = j & 31;
            const int mBase = (mtl >> 1) * 2048 + tq * 128 + (mtl & 1) * 64;
            const int nBase = nt * 64;

            float acc[8][8];
            #pragma unroll
            for (int i = 0; i < 8; i++)
                #pragma unroll
                for (int jj = 0; jj < 8; jj++) acc[i][jj] = 0.f;

            const float* Aptr = X  + (size_t)(mBase + gt) * E;
            const float* Bptr = Wx + (size_t)brr * G4 + nBase + brg * 16;

            // prefetch stage 0
            float4 avp[4], bvp[4];
            #pragma unroll
            for (int c = 0; c < 4; c++) {
                avp[c] = *(const float4*)(Aptr + c * 4);
                bvp[c] = *(const float4*)(Bptr + (size_t)(c == 0 ? 0 : 0) * G4 + 0) ;
            }
            // (B prefetch corrected below: rows brr + k0, 4 float4 across n)
            #pragma unroll
            for (int c = 0; c < 4; c++)
                bvp[c] = *(const float4*)(Bptr + c * 4);

            for (int k0 = 0; k0 < E; k0 += 16) {
                barn(5, 64);   // previous compute done before overwrite
                // A transpose store: As[k][m], k = 0..15 of this stage
                #pragma unroll
                for (int c = 0; c < 4; c++) {
                    As[(c * 4 + 0) * GEMM_AS_STRIDE + gt] = avp[c].x;
                    As[(c * 4 + 1) * GEMM_AS_STRIDE + gt] = avp[c].y;
                    As[(c * 4 + 2) * GEMM_AS_STRIDE + gt] = avp[c].z;
                    As[(c * 4 + 3) * GEMM_AS_STRIDE + gt] = avp[c].w;
                }
                // B store: row brr, cols brg*16 + 0..15
                #pragma unroll
                for (int c = 0; c < 4; c++)
                    *(float4*)&Bs[brr * GEMM_BS_STRIDE + brg * 16 + c * 4] =
                        bvp[c];
                barn(5, 64);
                // prefetch next stage while computing this one
                if (k0 + 16 < E) {
                    #pragma unroll
                    for (int c = 0; c < 4; c++) {
                        avp[c] = *(const float4*)(Aptr + k0 + 16 + c * 4);
                        bvp[c] = *(const float4*)(Bptr +
                                 (size_t)(k0 + 16) * G4 + c * 4);
                    }
                }
                #pragma unroll
                for (int k = 0; k < 16; k++) {
                    float4 a0 = *(const float4*)&As[k * GEMM_AS_STRIDE + tm];
                    float4 a1 = *(const float4*)&As[k * GEMM_AS_STRIDE + tm + 4];
                    float4 b0 = *(const float4*)&Bs[k * GEMM_BS_STRIDE + tn];
                    float4 b1 = *(const float4*)&Bs[k * GEMM_BS_STRIDE + tn + 4];
                    float aa[8] = { a0.x, a0.y, a0.z, a0.w,
                                    a1.x, a1.y, a1.z, a1.w };
                    float bb[8] = { b0.x, b0.y, b0.z, b0.w,
                                    b1.x, b1.y, b1.z, b1.w };
                    #pragma unroll
                    for (int i = 0; i < 8; i++)
                        #pragma unroll
                        for (int jj = 0; jj < 8; jj++)
                            acc[i][jj] = fmaf(aa[i], bb[jj], acc[i][jj]);
                }
            }

            float bsum[8];
            #pragma unroll
            for (int jj = 0; jj < 8; jj++)
                bsum[jj] = bx[nBase + tn + jj] + bh[nBase + tn + jj];

            #pragma unroll
            for (int i = 0; i < 8; i++) {
                size_t row = (size_t)(mBase + tm + i);
                float4 v0 = make_float4(acc[i][0] + bsum[0], acc[i][1] + bsum[1],
                                        acc[i][2] + bsum[2], acc[i][3] + bsum[3]);
                float4 v1 = make_float4(acc[i][4] + bsum[4], acc[i][5] + bsum[5],
                                        acc[i][6] + bsum[6], acc[i][7] + bsum[7]);
                *(float4*)&g_xg[row * G4 + nBase + tn]     = v0;
                *(float4*)&g_xg[row * G4 + nBase + tn + 4] = v1;
            }

            // release every 2nd tile (counter target 1024 per chunk)
            if (tile & 1) {
                barn(5, 64);               // both tiles' stores done
                if (gt == 0) red_release_add(&g_chunk[tq], 1u);
            }
        }
    }
}

// =====================================================================
extern "C" void kernel_launch(void* const* d_in, const int* in_sizes, int n_in,
                              void* d_out, int out_size)
{
    const float* x  = (const float*)d_in[0];
    const float* Wx = (const float*)d_in[1];
    const float* Wh = (const float*)d_in[2];
    const float* bx = (const float*)d_in[3];
    const float* bh = (const float*)d_in[4];
    float* out = (float*)d_out;

    reset_ctr_kernel<<<1, 32>>>();

    const int smem_bytes = (SM_GEMM_BASE + SM_GEMM_FLOATS) * (int)sizeof(float);
    cudaFuncSetAttribute(lstm_fused_kernel,
                         cudaFuncAttributeMaxDynamicSharedMemorySize, smem_bytes);
    lstm_fused_kernel<<<NCTA, THREADS, smem_bytes>>>(x, Wx, Wh, bx, bh, out);
}

// round 15
// speedup vs baseline: 2.0900x; 2.0900x over previous
#include <cuda_runtime.h>
#include <cstdint>
#include <cstddef>

#define B   32
#define T   2048
#define E   512
#define H   512
#define G4  2048
#define NCTA 128
#define THREADS 384          // 256 recurrence + 128 GEMM
#define HS_STRIDE  516
#define HS_STRIDE4 129

#define SM_RED_BASE   (48 * HS_STRIDE)                // floats
#define SM_GEMM_BASE  (SM_RED_BASE + 1024 * 4)        // floats
#define AS_STRIDE 132
#define BS_STRIDE 68
#define SM_GEMM_FLOATS (16 * AS_STRIDE + 16 * BS_STRIDE)

// ---- device scratch ----
__device__ float g_xg[(size_t)B * T * G4];
__device__ float g_hbuf[2][B * H];        // [parity][32 x 512]
__device__ unsigned g_bar;                // recurrence arrival counter
__device__ unsigned g_chunk[16];          // per-128-timestep xg readiness

__device__ __forceinline__ void barn(int id, int cnt) {
    asm volatile("bar.sync %0, %1;" :: "r"(id), "r"(cnt) : "memory");
}
__device__ __forceinline__ unsigned ld_acq(const unsigned* p) {
    unsigned v;
    asm volatile("ld.acquire.gpu.global.u32 %0, [%1];" : "=r"(v) : "l"(p));
    return v;
}
__device__ __forceinline__ void red_release_add(unsigned* p, unsigned v) {
    asm volatile("red.release.gpu.global.add.u32 [%0], %1;" :: "l"(p), "r"(v)
                 : "memory");
}
__device__ __forceinline__ float sigm(float x) {
    return 1.f / (1.f + __expf(-x));
}
__device__ __forceinline__ float tanh_fast(float x) {
    return 2.f / (1.f + __expf(-2.f * x)) - 1.f;
}

__global__ void reset_ctr_kernel() {
    if (threadIdx.x == 0) g_bar = 0;
    if (threadIdx.x < 16) g_chunk[threadIdx.x] = 0;
}

// =====================================================================
// Fused persistent kernel. 128 CTAs x 384 threads.
//  warps 0-7  : recurrence, single team, all 32 batches (R2/R4 layout:
//               warp w = k-slice [w*64,+64), lane tile 4b x 4gates ->
//               8 LDS.128 per 128 FMA per q — lowest crossbar pressure)
//  warps 8-11 : xg GEMM producer — 128x64 tiles, 8m x 8n per thread,
//               register-prefetched stages. 8 tiles/chunk/CTA,
//               release per tile -> g_chunk target 1024.
// =====================================================================
__global__ __launch_bounds__(THREADS, 1) void lstm_fused_kernel(
    const float* __restrict__ X,  const float* __restrict__ Wx,
    const float* __restrict__ Wh, const float* __restrict__ bx,
    const float* __restrict__ bh, float* __restrict__ out)
{
    extern __shared__ float sm[];
    float*  whs  = sm;                                 // 16 x 516
    float*  hsf  = sm + 16 * HS_STRIDE;                // 32 x 516
    float4* red4 = (float4*)(sm + SM_RED_BASE);        // 1024 float4

    const int tid = threadIdx.x;
    const int cta = blockIdx.x;

    // ---- common init ----
    for (int idx = tid; idx < 16 * 512; idx += THREADS) {
        int c = idx >> 9;
        int k = idx & 511;
        int col = ((c >> 2) << 9) + cta * 4 + (c & 3);
        whs[c * HS_STRIDE + k] = Wh[(size_t)k * G4 + col];
    }
    for (int idx = tid; idx < 32 * HS_STRIDE; idx += THREADS)
        hsf[idx] = 0.f;
    __syncthreads();   // only full-block sync

    if (tid < 256) {
        // =========================== RECURRENCE ======================
        const int lane = tid & 31;
        const int w    = tid >> 5;          // 0..7

        const int lb = lane & 7;            // b = lb + 8j
        const int lc = lane >> 3;           // gate 0..3 (c = lc + 4i)
        const float4* whs4 = (const float4*)whs;
        const float4* hs4  = (const float4*)hsf;
        float4*       hs4w = (float4*)hsf;

        const int rj  = tid >> 5;                  // reducers tid<128
        const int rB  = (lane & 7) + 8 * rj;
        const int hid = cta * 4 + (lane >> 3);
        float c_state = 0.f;

        for (int t = 0; t < T; t++) {
            // gate on xg chunk readiness (once per 128 steps)
            if ((t & 127) == 0) {
                if (tid == 0) {
                    const unsigned* cc = &g_chunk[t >> 7];
                    int spins = 0;
                    while (ld_acq(cc) < 1024u) {
                        if (++spins > 16) __nanosleep(128);
                    }
                }
                barn(1, 256);
            }

            // xg prefetch for epilogue
            float xp0 = 0.f, xp1 = 0.f, xp2 = 0.f, xp3 = 0.f;
            if (tid < 128) {
                const float* xr = g_xg + ((size_t)rB * T + t) * G4 + hid;
                xp0 = __ldcs(xr);
                xp1 = __ldcs(xr + 512);
                xp2 = __ldcs(xr + 1024);
                xp3 = __ldcs(xr + 1536);
            }

            if (t > 0) {
                if (tid == 0) {
                    unsigned target = 128u * (unsigned)t;
                    int spins = 0;
                    while (ld_acq(&g_bar) < target) {
                        if (++spins > 64) __nanosleep(64);
                    }
                }
                barn(1, 256);
                // reload h(t-1): 4096 float4 over 256 threads
                const float4* src = (const float4*)g_hbuf[(t - 1) & 1];
                #pragma unroll
                for (int q = 0; q < 16; q++) {
                    int v  = tid + 256 * q;
                    int b  = v >> 7;
                    int kk = v & 127;
                    hs4w[b * HS_STRIDE4 + kk] = __ldcg(src + v);
                }
                barn(1, 256);
            }

            // mainloop: k-slice [w*64,+64), 4b x 4gate
            float acc[4][4];
            #pragma unroll
            for (int j = 0; j < 4; j++)
                #pragma unroll
                for (int i = 0; i < 4; i++) acc[j][i] = 0.f;

            const int kb = w * 16;
            #pragma unroll 4
            for (int q = 0; q < 16; q++) {
                const int kv = kb + q;
                float4 wv[4];
                #pragma unroll
                for (int i = 0; i < 4; i++)
                    wv[i] = whs4[(lc + 4 * i) * HS_STRIDE4 + kv];
                #pragma unroll
                for (int j = 0; j < 4; j++) {
                    float4 hh = hs4[(lb + 8 * j) * HS_STRIDE4 + kv];
                    #pragma unroll
                    for (int i = 0; i < 4; i++) {
                        acc[j][i] = fmaf(hh.x, wv[i].x, acc[j][i]);
                        acc[j][i] = fmaf(hh.y, wv[i].y, acc[j][i]);
                        acc[j][i] = fmaf(hh.z, wv[i].z, acc[j][i]);
                        acc[j][i] = fmaf(hh.w, wv[i].w, acc[j][i]);
                    }
                }
            }

            #pragma unroll
            for (int j = 0; j < 4; j++)
                red4[j * 256 + w * 32 + lane] =
                    make_float4(acc[j][0], acc[j][1], acc[j][2], acc[j][3]);
            barn(1, 256);

            if (tid < 128) {
                float4 s = make_float4(0.f, 0.f, 0.f, 0.f);
                #pragma unroll
                for (int ww = 0; ww < 8; ww++) {
                    float4 v = red4[rj * 256 + ww * 32 + lane];
                    s.x += v.x; s.y += v.y; s.z += v.z; s.w += v.w;
                }
                float f  = sigm(s.x + xp0);
                float ig = sigm(s.y + xp1);
                float cc = tanh_fast(s.z + xp2);
                float og = sigm(s.w + xp3);
                c_state = f * c_state + ig * cc;
                float h_new = og * tanh_fast(c_state);
                g_hbuf[t & 1][rB * H + hid] = h_new;
                if (t == T - 1) {
                    out[rB * H + hid]         = h_new;
                    out[B * H + rB * H + hid] = c_state;
                }
                barn(2, 128);                    // order 128 h stores
                if (tid == 0) red_release_add(&g_bar, 1u);
            }
        }
    } else {
        // ============================ GEMM ===========================
        // warps 8-11 (128 threads). 128x64 tiles, 8m x 8n per thread.
        // Chunk tq: global tile j = cta + i*128 (i=0..7), b = j>>5,
        // nt = j&31; mBase = b*2048 + tq*128, nBase = nt*64.
        const int gt = tid - 256;                     // 0..127
        float* As = sm + SM_GEMM_BASE;                // [16][132] (k,m)
        float* Bs = As + 16 * AS_STRIDE;              // [16][68]  (k,n)

        const int tm  = (gt >> 3) * 8;                // 0..120
        const int tn  = (gt & 7) * 8;                 // 0..56
        const int brw = gt >> 3;                      // 0..15  B k-row
        const int bcl = (gt & 7) * 8;                 // B col

        for (int tile = 0; tile < 128; tile++) {
            const int tq = tile >> 3;
            const int j  = cta + ((tile & 7) << 7);
            const int bb = j >> 5;
            const int nt = j & 31;
            const int mBase = bb * 2048 + tq * 128;
            const int nBase = nt * 64;

            float acc[8][8];
            #pragma unroll
            for (int i = 0; i < 8; i++)
                #pragma unroll
                for (int jj = 0; jj < 8; jj++) acc[i][jj] = 0.f;

            const float* Aptr = X  + (size_t)(mBase + gt) * E;
            const float* Bptr = Wx + (size_t)brw * G4 + nBase + bcl;

            // prefetch stage 0
            float4 avp[4], bvp[2];
            #pragma unroll
            for (int c = 0; c < 4; c++)
                avp[c] = *(const float4*)(Aptr + c * 4);
            bvp[0] = *(const float4*)(Bptr);
            bvp[1] = *(const float4*)(Bptr + 4);

            for (int k0 = 0; k0 < E; k0 += 16) {
                barn(3, 128);    // previous stage's compute done
                // A transpose store: As[k][m], 16 k of this stage
                #pragma unroll
                for (int c = 0; c < 4; c++) {
                    As[(c * 4 + 0) * AS_STRIDE + gt] = avp[c].x;
                    As[(c * 4 + 1) * AS_STRIDE + gt] = avp[c].y;
                    As[(c * 4 + 2) * AS_STRIDE + gt] = avp[c].z;
                    As[(c * 4 + 3) * AS_STRIDE + gt] = avp[c].w;
                }
                // B store: row brw, cols bcl..bcl+8
                *(float4*)&Bs[brw * BS_STRIDE + bcl]     = bvp[0];
                *(float4*)&Bs[brw * BS_STRIDE + bcl + 4] = bvp[1];
                barn(3, 128);
                // prefetch next stage while computing this one
                if (k0 + 16 < E) {
                    #pragma unroll
                    for (int c = 0; c < 4; c++)
                        avp[c] = *(const float4*)(Aptr + k0 + 16 + c * 4);
                    bvp[0] = *(const float4*)(Bptr + (size_t)(k0 + 16) * G4);
                    bvp[1] = *(const float4*)(Bptr + (size_t)(k0 + 16) * G4 + 4);
                }
                #pragma unroll
                for (int k = 0; k < 16; k++) {
                    float4 a0 = *(const float4*)&As[k * AS_STRIDE + tm];
                    float4 a1 = *(const float4*)&As[k * AS_STRIDE + tm + 4];
                    float4 b0 = *(const float4*)&Bs[k * BS_STRIDE + tn];
                    float4 b1 = *(const float4*)&Bs[k * BS_STRIDE + tn + 4];
                    float aa[8] = { a0.x, a0.y, a0.z, a0.w,
                                    a1.x, a1.y, a1.z, a1.w };
                    float bbv[8] = { b0.x, b0.y, b0.z, b0.w,
                                     b1.x, b1.y, b1.z, b1.w };
                    #pragma unroll
                    for (int i = 0; i < 8; i++)
                        #pragma unroll
                        for (int jj = 0; jj < 8; jj++)
                            acc[i][jj] = fmaf(aa[i], bbv[jj], acc[i][jj]);
                }
            }

            float bsum[8];
            #pragma unroll
            for (int jj = 0; jj < 8; jj++)
                bsum[jj] = bx[nBase + tn + jj] + bh[nBase + tn + jj];

            #pragma unroll
            for (int i = 0; i < 8; i++) {
                size_t row = (size_t)(mBase + tm + i);
                float4 v0 = make_float4(acc[i][0] + bsum[0], acc[i][1] + bsum[1],
                                        acc[i][2] + bsum[2], acc[i][3] + bsum[3]);
                float4 v1 = make_float4(acc[i][4] + bsum[4], acc[i][5] + bsum[5],
                                        acc[i][6] + bsum[6], acc[i][7] + bsum[7]);
                *(float4*)&g_xg[row * G4 + nBase + tn]     = v0;
                *(float4*)&g_xg[row * G4 + nBase + tn + 4] = v1;
            }

            barn(3, 128);            // all 128 threads' xg stores done
            if (gt == 0) red_release_add(&g_chunk[tq], 1u);
        }
    }
}

// =====================================================================
extern "C" void kernel_launch(void* const* d_in, const int* in_sizes, int n_in,
                              void* d_out, int out_size)
{
    const float* x  = (const float*)d_in[0];
    const float* Wx = (const float*)d_in[1];
    const float* Wh = (const float*)d_in[2];
    const float* bx = (const float*)d_in[3];
    const float* bh = (const float*)d_in[4];
    float* out = (float*)d_out;

    reset_ctr_kernel<<<1, 32>>>();

    const int smem_bytes =
        (SM_GEMM_BASE + SM_GEMM_FLOATS) * (int)sizeof(float);
    cudaFuncSetAttribute(lstm_fused_kernel,
                         cudaFuncAttributeMaxDynamicSharedMemorySize, smem_bytes);
    lstm_fused_kernel<<<NCTA, THREADS, smem_bytes>>>(x, Wx, Wh, bx, bh, out);
}